// round 2
// baseline (speedup 1.0000x reference)
#include <cuda_runtime.h>
#include <cstdint>

#define HW   48000
#define NPTS 12000
#define KNN  16

using ull = unsigned long long;

__device__ __forceinline__ ull pack2(float x, float y) {
    ull r; asm("mov.b64 %0, {%1, %2};" : "=l"(r) : "f"(x), "f"(y)); return r;
}
__device__ __forceinline__ float2 unpack2(ull v) {
    float2 r; asm("mov.b64 {%0, %1}, %2;" : "=f"(r.x), "=f"(r.y) : "l"(v)); return r;
}
__device__ __forceinline__ ull fma2(ull a, ull b, ull c) {
    ull d; asm("fma.rn.f32x2 %0, %1, %2, %3;" : "=l"(d) : "l"(a), "l"(b), "l"(c)); return d;
}

// transposed feature map: [b*HW + p][64], contiguous 256B per pixel
__device__ __align__(16) float g_ft[2u * HW * 64u];

// ---------------------------------------------------------------------------
// Kernel 1: f = leaky_relu(mlp_w @ features + mlp_b), transposed to [pix][c]
// grid: 750 blocks x 128 threads, 1 pixel per thread
// ---------------------------------------------------------------------------
__global__ void __launch_bounds__(128) k_feat_mlp(
    const float* __restrict__ feat,   // [B,64,HW]
    const float* __restrict__ mw,     // [64,64] row-major [cout][cin]
    const float* __restrict__ mb)     // [64]
{
    // ws[ci][q] holds packed pairs for output channels (4q..4q+3) at input ci
    __shared__ __align__(16) ulonglong2 ws[64][16];
    __shared__ float bsh[64];
    __shared__ float stage[128 * 33];

    const int tid = threadIdx.x;
    for (int i = tid; i < 4096; i += 128) {
        int c = i >> 6, ci = i & 63;
        ((float*)&ws[ci][c >> 2])[c & 3] = mw[i];
    }
    if (tid < 64) bsh[tid] = mb[tid];
    __syncthreads();

    const long pix = (long)blockIdx.x * 128 + tid;        // 0..95999
    const int b = (pix >= HW) ? 1 : 0;
    const int p = (int)(pix - (long)b * HW);
    const float* fp = feat + (size_t)b * 64 * HW + p;

    ull acc[32];
#pragma unroll
    for (int q = 0; q < 32; q++) acc[q] = pack2(bsh[2 * q], bsh[2 * q + 1]);

#pragma unroll 4
    for (int ci = 0; ci < 64; ci++) {
        float v = fp[(size_t)ci * HW];
        ull vv = pack2(v, v);
#pragma unroll
        for (int q = 0; q < 16; q++) {
            ulonglong2 w2v = ws[ci][q];
            acc[2 * q]     = fma2(w2v.x, vv, acc[2 * q]);
            acc[2 * q + 1] = fma2(w2v.y, vv, acc[2 * q + 1]);
        }
    }

    const size_t base = (size_t)blockIdx.x * 128 * 64;
#pragma unroll
    for (int h = 0; h < 2; h++) {
#pragma unroll
        for (int q = 0; q < 16; q++) {
            float2 t = unpack2(acc[h * 16 + q]);
            t.x = (t.x >= 0.f) ? t.x : 0.1f * t.x;
            t.y = (t.y >= 0.f) ? t.y : 0.1f * t.y;
            stage[tid * 33 + 2 * q]     = t.x;
            stage[tid * 33 + 2 * q + 1] = t.y;
        }
        __syncthreads();
        for (int i = tid; i < 4096; i += 128) {
            int pl = i >> 5, cc = i & 31;
            g_ft[base + (size_t)pl * 64 + h * 32 + cc] = stage[pl * 33 + cc];
        }
        __syncthreads();
    }
}

// ---------------------------------------------------------------------------
// Kernel 2: gather + weight-net + f*wgt max over k
// grid: 750 blocks x 128 threads; 1 warp = 8 points, block = 32 points
// ---------------------------------------------------------------------------
__global__ void __launch_bounds__(128) k_gather(
    const float* __restrict__ xyz,    // [B,3,HW]
    const float* __restrict__ sxyz,   // [B,3,N]
    const int*   __restrict__ knn,    // [B,N,16]
    const int*   __restrict__ mask,   // [B,N,16]  (bool widened to int32)
    const float* __restrict__ w1, const float* __restrict__ b1,
    const float* __restrict__ w2, const float* __restrict__ b2,
    const float* __restrict__ w3, const float* __restrict__ b3,
    float* __restrict__ out)          // [B,64,N]
{
    __shared__ float s_w1[24];
    __shared__ float s_b1[8];
    __shared__ float s_w2[256];
    __shared__ float s_b2[32];
    __shared__ __align__(8) float s_h2[4][16][34];  // PAD=34: conflict-free + 8B rows
    __shared__ int   s_idx[4][16];
    __shared__ float s_mf[4][16];
    __shared__ float s_out[64][33];

    const int tid = threadIdx.x;
    const int w = tid >> 5, lane = tid & 31;

    if (tid < 24) s_w1[tid] = w1[tid];
    if (tid < 8)  s_b1[tid] = b1[tid];
    if (tid < 32) s_b2[tid] = b2[tid];
    for (int i = tid; i < 256; i += 128) s_w2[i] = w2[i];

    // w3 rows for this lane's two channels, packed over reduction pairs
    const int c0 = 2 * lane, c1 = c0 + 1;
    ull w3p0[16], w3p1[16];
    const ull* w3u = reinterpret_cast<const ull*>(w3);
#pragma unroll
    for (int e = 0; e < 16; e++) {
        w3p0[e] = w3u[c0 * 16 + e];
        w3p1[e] = w3u[c1 * 16 + e];
    }
    const float b3c0 = b3[c0], b3c1 = b3[c1];
    __syncthreads();

    const int b = blockIdx.x / 375;                    // 375 blocks per batch
    const int n_block = (blockIdx.x % 375) * 32;

    const float* xyz_b = xyz + (size_t)b * 3 * HW;
    const float* sx_b  = sxyz + (size_t)b * 3 * NPTS;
    const float* ftb   = g_ft + (size_t)b * HW * 64;

    const int j = lane & 15, half = lane >> 4;

    for (int pt = 0; pt < 8; pt++) {
        const int slot = w * 8 + pt;
        const int n = n_block + slot;

        // ---- phase 1: weight-net hidden layers, lane pair (j, j+16) per neighbor
        {
            const long kbase = ((long)b * NPTS + n) * KNN + j;
            const int p = knn[kbase];
            const int mv = (mask[kbase] != 0);
            const float sxv = sx_b[n];
            const float syv = sx_b[NPTS + n];
            const float szv = sx_b[2 * NPTS + n];
            const float kx = mv ? xyz_b[p] : 0.f;
            const float ky = mv ? xyz_b[HW + p] : 0.f;
            const float kz = mv ? xyz_b[2 * HW + p] : 0.f;
            const float ox = kx - sxv, oy = ky - syv, oz = kz - szv;

            float h1[8];
#pragma unroll
            for (int r = 0; r < 8; r++) {
                float t = s_b1[r] + s_w1[3 * r] * ox + s_w1[3 * r + 1] * oy
                        + s_w1[3 * r + 2] * oz;
                h1[r] = fmaxf(t, 0.f);
            }
#pragma unroll
            for (int mm = 0; mm < 16; mm++) {
                const int m = half * 16 + mm;
                float t = s_b2[m];
#pragma unroll
                for (int r = 0; r < 8; r++) t += s_w2[m * 8 + r] * h1[r];
                s_h2[w][j][m] = fmaxf(t, 0.f);
            }
            if (half == 0) { s_idx[w][j] = p; s_mf[w][j] = mv ? 1.f : 0.f; }
        }
        __syncwarp();

        // ---- phase 2: w3 layer (packed over reduction) + f*wgt max over k
        float accx = -3.4e38f, accy = -3.4e38f;
#pragma unroll 2
        for (int jj = 0; jj < KNN; jj++) {
            const int p = s_idx[w][jj];
            const float mf = s_mf[w][jj];
            const float2 fv = *reinterpret_cast<const float2*>(
                ftb + (size_t)p * 64 + c0);
            const ull* h2p = reinterpret_cast<const ull*>(&s_h2[w][jj][0]);
            ull wa0 = 0ull, wa1 = 0ull;
#pragma unroll
            for (int e = 0; e < 16; e++) {
                const ull hh = h2p[e];        // broadcast LDS.64
                wa0 = fma2(w3p0[e], hh, wa0);
                wa1 = fma2(w3p1[e], hh, wa1);
            }
            const float2 a0 = unpack2(wa0), a1 = unpack2(wa1);
            const float wg0 = fmaxf(a0.x + a0.y + b3c0, 0.f);
            const float wg1 = fmaxf(a1.x + a1.y + b3c1, 0.f);
            accx = fmaxf(accx, fv.x * mf * wg0);
            accy = fmaxf(accy, fv.y * mf * wg1);
        }
        s_out[c0][slot] = accx;
        s_out[c1][slot] = accy;
        __syncwarp();
    }
    __syncthreads();

    // coalesced output: [B,64,N]
    float* outb = out + (size_t)b * 64 * NPTS;
    for (int i = tid; i < 2048; i += 128) {
        const int c = i >> 5, s = i & 31;
        outb[(size_t)c * NPTS + n_block + s] = s_out[c][s];
    }
}

extern "C" void kernel_launch(void* const* d_in, const int* in_sizes, int n_in,
                              void* d_out, int out_size)
{
    const float* xyz  = (const float*)d_in[0];
    const float* feat = (const float*)d_in[1];
    const float* sx   = (const float*)d_in[2];
    const int*   knn  = (const int*)d_in[3];
    const int*   mask = (const int*)d_in[4];
    const float* mw = (const float*)d_in[5];
    const float* mb = (const float*)d_in[6];
    const float* w1 = (const float*)d_in[7];
    const float* b1 = (const float*)d_in[8];
    const float* w2 = (const float*)d_in[9];
    const float* b2 = (const float*)d_in[10];
    const float* w3 = (const float*)d_in[11];
    const float* b3 = (const float*)d_in[12];
    float* out = (float*)d_out;

    k_feat_mlp<<<750, 128>>>(feat, mw, mb);
    k_gather<<<750, 128>>>(xyz, sx, knn, mask, w1, b1, w2, b2, w3, b3, out);
}